// round 3
// baseline (speedup 1.0000x reference)
#include <cuda_runtime.h>
#include <math.h>

#define TPB 256
#define PPB 128   // pairs per block (half-block role split)

__device__ float g_partials[2048];
__device__ unsigned int g_count;

__device__ __forceinline__ void box_corners(float x, float y, float w, float l,
                                            float im, float re,
                                            float* cx, float* cy) {
    // cos(atan2(im,re)) = re/r, sin(atan2(im,re)) = im/r
    float rinv = rsqrtf(fmaf(im, im, re * re));
    float c = re * rinv;
    float s = im * rinv;
    float hw = 0.5f * w, hl = 0.5f * l;
    cx[0] = x - hw * c - hl * s;  cy[0] = y - hw * s + hl * c;
    cx[1] = x - hw * c + hl * s;  cy[1] = y - hw * s - hl * c;
    cx[2] = x + hw * c + hl * s;  cy[2] = y + hw * s - hl * c;
    cx[3] = x + hw * c - hl * s;  cy[3] = y + hw * s + hl * c;
}

// One Sutherland-Hodgman clip pass, fully registerized, with select chains
// bounded by the invariant nn <= 2j at candidate step j.
// Reference semantics: keep = (val <= 0), crossing = strict sign change,
// frozen = empty result -> keep pre-clip polygon, stop.
template <int INCAP, int OUTCAP>
__device__ __forceinline__ void clip_edge(float a, float b, float c,
                                          float (&ax)[8], float (&ay)[8],
                                          int& np, bool& frozen) {
    if (frozen || np <= 2) return;

    float v[INCAP];
#pragma unroll
    for (int j = 0; j < INCAP; j++)
        v[j] = a * ax[j] + b * ay[j] + c;

    float bx[8], by[8];
#pragma unroll
    for (int s = 0; s < OUTCAP; s++) { bx[s] = 0.0f; by[s] = 0.0f; }

    int nn = 0;
#pragma unroll
    for (int j = 0; j < INCAP; j++) {
        bool act  = (j < np);
        bool last = (j + 1 == np);
        const int j1 = (j + 1 < INCAP) ? (j + 1) : 0;
        float tv = last ? v[0]  : v[j1];
        float tx = last ? ax[0] : ax[j1];
        float ty = last ? ay[0] : ay[j1];

        bool keep = act && (v[j] <= 0.0f);
        bool crs  = act && (v[j] * tv < 0.0f);

        // keep push: nn in [0, min(2j, OUTCAP-1)]
        const int KMAX = (2 * j < OUTCAP - 1) ? 2 * j : OUTCAP - 1;
#pragma unroll
        for (int s = 0; s <= KMAX; s++) {
            bool w = keep && (nn == s);
            bx[s] = w ? ax[j] : bx[s];
            by[s] = w ? ay[j] : by[s];
        }
        nn += keep ? 1 : 0;

        float a2 = ty - ay[j];
        float b2 = ax[j] - tx;
        float c2 = tx * ay[j] - ty * ax[j];
        float wd = a * b2 - b * a2;
        float iw = __fdividef(1.0f, wd);
        float ix = (b * c2 - c * b2) * iw;
        float iy = (c * a2 - a * c2) * iw;

        // crossing push: nn in [0, min(2j+1, OUTCAP-1)]
        const int CMAX = (2 * j + 1 < OUTCAP - 1) ? 2 * j + 1 : OUTCAP - 1;
#pragma unroll
        for (int s = 0; s <= CMAX; s++) {
            bool w = crs && (nn == s);
            bx[s] = w ? ix : bx[s];
            by[s] = w ? iy : by[s];
        }
        nn += crs ? 1 : 0;
    }

    if (nn > 0) {
        np = (nn < OUTCAP) ? nn : OUTCAP;
#pragma unroll
        for (int s = 0; s < OUTCAP; s++) { ax[s] = bx[s]; ay[s] = by[s]; }
    } else {
        frozen = true;  // keep old polygon (reference semantics)
    }
}

__global__ void __launch_bounds__(TPB)
giou_kernel(const float* __restrict__ pred,
            const float* __restrict__ tgt,
            float* __restrict__ out, int n) {
    int tid  = threadIdx.x;
    int lp   = tid & (PPB - 1);     // pair slot within block
    int role = tid >> 7;            // 0 = clip/iou, 1 = hull
    int i    = blockIdx.x * PPB + lp;
    bool active = (i < n);

    __shared__ float sm_uni[PPB];

    float pcx[4], pcy[4], tcx[4], tcy[4];
    if (active) {
        const float2* pb = (const float2*)(pred + 6 * i);
        const float2* tb = (const float2*)(tgt + 6 * i);
        float2 p0 = __ldg(pb), p1 = __ldg(pb + 1), p2 = __ldg(pb + 2);
        float2 t0 = __ldg(tb), t1 = __ldg(tb + 1), t2 = __ldg(tb + 2);
        box_corners(p0.x, p0.y, p1.x, p1.y, p2.x, p2.y, pcx, pcy);
        box_corners(t0.x, t0.y, t1.x, t1.y, t2.x, t2.y, tcx, tcy);
        if (role == 0) {
            // stash areas for later (recompute cheap): keep w*l in registers
        }
    }

    float hull = 0.0f;   // role 1 result
    float term = 0.0f;   // this thread's contribution to sum(giou)

    if (role == 0) {
        if (active) {
            const float2* pb = (const float2*)(pred + 6 * i);
            const float2* tb = (const float2*)(tgt + 6 * i);
            float2 pwl = __ldg(pb + 1);
            float2 twl = __ldg(tb + 1);

            // ---- clip pred quad by target quad ----
            float ax[8], ay[8];
#pragma unroll
            for (int k = 0; k < 4; k++) { ax[k] = pcx[k]; ay[k] = pcy[k]; }
#pragma unroll
            for (int k = 4; k < 8; k++) { ax[k] = pcx[0]; ay[k] = pcy[0]; }
            int np = 4;
            bool frozen = false;

            float a0 = tcy[1] - tcy[0], b0 = tcx[0] - tcx[1];
            float c0 = tcx[1] * tcy[0] - tcy[1] * tcx[0];
            clip_edge<4, 5>(a0, b0, c0, ax, ay, np, frozen);
            float a1 = tcy[2] - tcy[1], b1 = tcx[1] - tcx[2];
            float c1 = tcx[2] * tcy[1] - tcy[2] * tcx[1];
            clip_edge<5, 6>(a1, b1, c1, ax, ay, np, frozen);
            float a2 = tcy[3] - tcy[2], b2 = tcx[2] - tcx[3];
            float c2 = tcx[3] * tcy[2] - tcy[3] * tcx[2];
            clip_edge<6, 7>(a2, b2, c2, ax, ay, np, frozen);
            float a3 = tcy[0] - tcy[3], b3 = tcx[3] - tcx[0];
            float c3 = tcx[0] * tcy[3] - tcy[0] * tcx[3];
            clip_edge<7, 8>(a3, b3, c3, ax, ay, np, frozen);

            // ---- shoelace ----
            float s2 = 0.0f;
#pragma unroll
            for (int j = 0; j < 8; j++) {
                bool act = (j < np);
                bool last = (j + 1 == np);
                const int j1 = (j + 1) & 7;
                float nx = last ? ax[0] : ax[j1];
                float ny = last ? ay[0] : ay[j1];
                float t = ax[j] * ny - ay[j] * nx;
                s2 += act ? t : 0.0f;
            }
            float inter = (np > 2) ? 0.5f * fabsf(s2) : 0.0f;

            float uni = pwl.x * pwl.y + twl.x * twl.y - inter;
            float iou = inter / (uni + 1e-16f);
            out[i] = iou;
            sm_uni[lp] = uni;
            term = 1.0f - iou;
        }
    } else {
        if (active) {
            // ---- convex hull area (reference all-pairs form),
            //      with cross-product sharing: test of edge (i,j) at k is
            //      cr[j][k]; test of edge (i,k) at j is -cr[j][k].
            float hx[8], hy[8];
#pragma unroll
            for (int k = 0; k < 4; k++) {
                hx[k] = pcx[k];     hy[k] = pcy[k];
                hx[4 + k] = tcx[k]; hy[4 + k] = tcy[k];
            }
            float hs = 0.0f;
#pragma unroll
            for (int ii = 0; ii < 8; ii++) {
                float dx[8], dy[8];
#pragma unroll
                for (int k = 0; k < 8; k++) {
                    dx[k] = hx[k] - hx[ii];
                    dy[k] = hy[k] - hy[ii];
                }
                float cc[8][8];
#pragma unroll
                for (int j = 0; j < 8; j++) {
                    if (j == ii) continue;
#pragma unroll
                    for (int k = j + 1; k < 8; k++) {
                        if (k == ii) continue;
                        cc[j][k] = dx[j] * dy[k] - dy[j] * dx[k];
                    }
                }
#pragma unroll
                for (int jj = 0; jj < 8; jj++) {
                    if (jj == ii) continue;
                    bool ok = (dx[jj] * dx[jj] + dy[jj] * dy[jj] > 1e-12f);
#pragma unroll
                    for (int k = 0; k < 8; k++) {
                        if (k == ii || k == jj) continue;
                        float cr = (jj < k) ? cc[jj][k] : -cc[k][jj];
                        ok = ok && (cr >= -1e-6f);
                    }
                    float contrib = hx[ii] * hy[jj] - hy[ii] * hx[jj];
                    hs += ok ? contrib : 0.0f;
                }
            }
            hull = 0.5f * fabsf(hs);
        }
    }

    __syncthreads();

    if (role == 1 && active) {
        float uni = sm_uni[lp];
        term = (hull - uni) / (hull + 1e-16f);
    }

    // ---- deterministic in-kernel reduction of `term` ----
#pragma unroll
    for (int off = 16; off > 0; off >>= 1)
        term += __shfl_down_sync(0xffffffffu, term, off);

    __shared__ float wsum[TPB / 32];
    __shared__ bool isLast;
    if ((tid & 31) == 0) wsum[tid >> 5] = term;
    __syncthreads();

    if (tid == 0) {
        float bs = 0.0f;
#pragma unroll
        for (int w = 0; w < TPB / 32; w++) bs += wsum[w];
        g_partials[blockIdx.x] = bs;
        __threadfence();
        unsigned c = atomicAdd(&g_count, 1u);
        isLast = (c == gridDim.x - 1);
    }
    __syncthreads();

    if (isLast) {
        __threadfence();
        float v = 0.0f;
        for (int j = tid; j < (int)gridDim.x; j += TPB)
            v += ((volatile float*)g_partials)[j];
#pragma unroll
        for (int off = 16; off > 0; off >>= 1)
            v += __shfl_down_sync(0xffffffffu, v, off);
        if ((tid & 31) == 0) wsum[tid >> 5] = v;
        __syncthreads();
        if (tid == 0) {
            float tot = 0.0f;
#pragma unroll
            for (int w = 0; w < TPB / 32; w++) tot += wsum[w];
            out[n] = tot;
            g_count = 0;  // reset for next graph replay
        }
    }
}

extern "C" void kernel_launch(void* const* d_in, const int* in_sizes, int n_in,
                              void* d_out, int out_size) {
    const float* pred = (const float*)d_in[0];
    const float* tgt  = (const float*)d_in[1];
    float* out = (float*)d_out;
    int n = in_sizes[0] / 6;
    int nblocks = (n + PPB - 1) / PPB;
    giou_kernel<<<nblocks, TPB>>>(pred, tgt, out, n);
}

// round 4
// speedup vs baseline: 1.2718x; 1.2718x over previous
#include <cuda_runtime.h>
#include <math.h>

#define TPB 128
#define NPART 2048

__device__ float g_partials[NPART];
__device__ unsigned int g_count;

__device__ __forceinline__ void box_corners(float x, float y, float w, float l,
                                            float im, float re,
                                            float* cx, float* cy) {
    // cos(atan2(im,re)) = re/r, sin(atan2(im,re)) = im/r
    float rinv = rsqrtf(fmaf(im, im, re * re));
    float c = re * rinv;
    float s = im * rinv;
    float hw = 0.5f * w, hl = 0.5f * l;
    cx[0] = x - hw * c - hl * s;  cy[0] = y - hw * s + hl * c;
    cx[1] = x - hw * c + hl * s;  cy[1] = y - hw * s - hl * c;
    cx[2] = x + hw * c + hl * s;  cy[2] = y + hw * s - hl * c;
    cx[3] = x + hw * c - hl * s;  cy[3] = y + hw * s + hl * c;
}

// One Sutherland-Hodgman clip pass. Polygon lives in a thread-private smem
// column (layout [slot][tid], stride TPB -> bank-conflict-free for any slot).
// Compaction "push" = predicated STS at computed address; no select chains.
// In-place safe: all INCAP slots are read into registers before any write.
// Reference semantics: keep = (val <= 0), crossing = strict sign change,
// frozen = empty result -> keep pre-clip polygon, stop clipping.
template <int INCAP>
__device__ __forceinline__ void clip_edge_smem(float a, float b, float c,
                                               float* __restrict__ sx,
                                               float* __restrict__ sy,
                                               int t, int& np, bool& frozen) {
    if (frozen || np <= 2) return;

    float rx[INCAP], ry[INCAP], v[INCAP];
#pragma unroll
    for (int j = 0; j < INCAP; j++) {
        rx[j] = sx[j * TPB + t];
        ry[j] = sy[j * TPB + t];
        v[j]  = a * rx[j] + b * ry[j] + c;
    }

    int nn = 0;
#pragma unroll
    for (int j = 0; j < INCAP; j++) {
        bool act  = (j < np);
        bool last = (j + 1 == np);
        const int j1 = (j + 1 < INCAP) ? (j + 1) : 0;
        float tv = last ? v[0]  : v[j1];
        float tx = last ? rx[0] : rx[j1];
        float ty = last ? ry[0] : ry[j1];

        bool keep = act && (v[j] <= 0.0f);
        bool crs  = act && (v[j] * tv < 0.0f);

        if (keep) {
            sx[nn * TPB + t] = rx[j];
            sy[nn * TPB + t] = ry[j];
            nn++;
        }
        if (crs) {
            float a2 = ty - ry[j];
            float b2 = rx[j] - tx;
            float c2 = tx * ry[j] - ty * rx[j];
            float wd = a * b2 - b * a2;
            float iw = __fdividef(1.0f, wd);
            sx[nn * TPB + t] = (b * c2 - c * b2) * iw;
            sy[nn * TPB + t] = (c * a2 - a * c2) * iw;
            nn++;
        }
    }

    if (nn > 0) np = nn;  // geometric bound: nn <= INCAP+1 <= 8
    else frozen = true;   // keep old polygon (reference semantics)
}

__global__ void __launch_bounds__(TPB)
giou_kernel(const float* __restrict__ pred,
            const float* __restrict__ tgt,
            float* __restrict__ out, int n) {
    __shared__ float s_x[8 * TPB];
    __shared__ float s_y[8 * TPB];

    int t = threadIdx.x;
    int i = blockIdx.x * TPB + t;
    float giou = 0.0f;

    if (i < n) {
        const float2* pb = (const float2*)(pred + 6 * i);
        const float2* tb = (const float2*)(tgt + 6 * i);
        float2 p0 = __ldg(pb), p1 = __ldg(pb + 1), p2 = __ldg(pb + 2);
        float2 t0 = __ldg(tb), t1 = __ldg(tb + 1), t2 = __ldg(tb + 2);

        float pcx[4], pcy[4], tcx[4], tcy[4];
        box_corners(p0.x, p0.y, p1.x, p1.y, p2.x, p2.y, pcx, pcy);
        box_corners(t0.x, t0.y, t1.x, t1.y, t2.x, t2.y, tcx, tcy);

        // ---- init polygon (pred quad) in this thread's smem column ----
#pragma unroll
        for (int k = 0; k < 4; k++) {
            s_x[k * TPB + t] = pcx[k];
            s_y[k * TPB + t] = pcy[k];
        }
#pragma unroll
        for (int k = 4; k < 8; k++) {   // defined values in spare slots
            s_x[k * TPB + t] = pcx[0];
            s_y[k * TPB + t] = pcy[0];
        }
        int np = 4;
        bool frozen = false;

        // ---- clip by the 4 target half-planes ----
        {
            float a0 = tcy[1] - tcy[0], b0 = tcx[0] - tcx[1];
            float c0 = tcx[1] * tcy[0] - tcy[1] * tcx[0];
            clip_edge_smem<4>(a0, b0, c0, s_x, s_y, t, np, frozen);
            float a1 = tcy[2] - tcy[1], b1 = tcx[1] - tcx[2];
            float c1 = tcx[2] * tcy[1] - tcy[2] * tcx[1];
            clip_edge_smem<5>(a1, b1, c1, s_x, s_y, t, np, frozen);
            float a2 = tcy[3] - tcy[2], b2 = tcx[2] - tcx[3];
            float c2 = tcx[3] * tcy[2] - tcy[3] * tcx[2];
            clip_edge_smem<6>(a2, b2, c2, s_x, s_y, t, np, frozen);
            float a3 = tcy[0] - tcy[3], b3 = tcx[3] - tcx[0];
            float c3 = tcx[0] * tcy[3] - tcy[0] * tcx[3];
            clip_edge_smem<7>(a3, b3, c3, s_x, s_y, t, np, frozen);
        }

        // ---- shoelace over final polygon ----
        float qx[8], qy[8];
#pragma unroll
        for (int k = 0; k < 8; k++) {
            qx[k] = s_x[k * TPB + t];
            qy[k] = s_y[k * TPB + t];
        }
        float s2 = 0.0f;
#pragma unroll
        for (int j = 0; j < 8; j++) {
            bool act  = (j < np);
            bool last = (j + 1 == np);
            const int j1 = (j + 1) & 7;
            float nx = last ? qx[0] : qx[j1];
            float ny = last ? qy[0] : qy[j1];
            float tm = qx[j] * ny - qy[j] * nx;
            s2 += act ? tm : 0.0f;
        }
        float inter = (np > 2) ? 0.5f * fabsf(s2) : 0.0f;

        float uni = p1.x * p1.y + t1.x * t1.y - inter;
        float iou = inter / (uni + 1e-16f);
        out[i] = iou;

        // ---- convex hull area (reference all-pairs form), antisymmetric:
        //      cross of edge (jj->ii) at k equals -cross of (ii->jj) at k,
        //      and contrib(jj,ii) = -contrib(ii,jj). Each unordered pair
        //      computed once, both directed validities derived.
        float hx[8], hy[8];
#pragma unroll
        for (int k = 0; k < 4; k++) {
            hx[k] = pcx[k];     hy[k] = pcy[k];
            hx[4 + k] = tcx[k]; hy[4 + k] = tcy[k];
        }
        float hs = 0.0f;
#pragma unroll
        for (int ii = 0; ii < 8; ii++) {
            float dx[8], dy[8];
#pragma unroll
            for (int k = 0; k < 8; k++) {
                dx[k] = hx[k] - hx[ii];
                dy[k] = hy[k] - hy[ii];
            }
#pragma unroll
            for (int jj = ii + 1; jj < 8; jj++) {
                float ex = dx[jj], ey = dy[jj];
                float len2 = ex * ex + ey * ey;
                bool okL = (len2 > 1e-12f);  // i->j direction
                bool okR = okL;              // j->i direction
#pragma unroll
                for (int k = 0; k < 8; k++) {
                    if (k == ii || k == jj) continue;  // cross == 0 there
                    float cr = ex * dy[k] - ey * dx[k];
                    okL = okL && (cr >= -1e-6f);
                    okR = okR && (cr <= 1e-6f);
                }
                float cij = hx[ii] * hy[jj] - hy[ii] * hx[jj];
                hs += okL ? cij : 0.0f;
                hs += okR ? -cij : 0.0f;
            }
        }
        float hull = 0.5f * fabsf(hs);

        giou = 1.0f - (iou - (hull - uni) / (hull + 1e-16f));
    }

    // ---- deterministic in-kernel reduction ----
#pragma unroll
    for (int off = 16; off > 0; off >>= 1)
        giou += __shfl_down_sync(0xffffffffu, giou, off);

    __shared__ float wsum[TPB / 32];
    __shared__ bool isLast;
    if ((t & 31) == 0) wsum[t >> 5] = giou;
    __syncthreads();

    if (t == 0) {
        float bs = 0.0f;
#pragma unroll
        for (int w = 0; w < TPB / 32; w++) bs += wsum[w];
        g_partials[blockIdx.x] = bs;
        __threadfence();
        unsigned c = atomicAdd(&g_count, 1u);
        isLast = (c == gridDim.x - 1);
    }
    __syncthreads();

    if (isLast) {
        __threadfence();
        float v = 0.0f;
        for (int j = t; j < (int)gridDim.x; j += TPB)
            v += ((volatile float*)g_partials)[j];
#pragma unroll
        for (int off = 16; off > 0; off >>= 1)
            v += __shfl_down_sync(0xffffffffu, v, off);
        if ((t & 31) == 0) wsum[t >> 5] = v;
        __syncthreads();
        if (t == 0) {
            float tot = 0.0f;
#pragma unroll
            for (int w = 0; w < TPB / 32; w++) tot += wsum[w];
            out[n] = tot;
            g_count = 0;  // reset for next graph replay
        }
    }
}

extern "C" void kernel_launch(void* const* d_in, const int* in_sizes, int n_in,
                              void* d_out, int out_size) {
    const float* pred = (const float*)d_in[0];
    const float* tgt  = (const float*)d_in[1];
    float* out = (float*)d_out;
    int n = in_sizes[0] / 6;
    int nblocks = (n + TPB - 1) / TPB;
    giou_kernel<<<nblocks, TPB>>>(pred, tgt, out, n);
}

// round 5
// speedup vs baseline: 1.3907x; 1.0935x over previous
#include <cuda_runtime.h>
#include <math.h>

#define TPB 128
#define NPART 2048

__device__ float g_partials[NPART];
__device__ unsigned int g_count;

__device__ __forceinline__ void box_corners(float x, float y, float w, float l,
                                            float im, float re,
                                            float* cx, float* cy) {
    // cos(atan2(im,re)) = re/r, sin(atan2(im,re)) = im/r
    float rinv = rsqrtf(fmaf(im, im, re * re));
    float c = re * rinv;
    float s = im * rinv;
    float hw = 0.5f * w, hl = 0.5f * l;
    cx[0] = x - hw * c - hl * s;  cy[0] = y - hw * s + hl * c;
    cx[1] = x - hw * c + hl * s;  cy[1] = y - hw * s - hl * c;
    cx[2] = x + hw * c + hl * s;  cy[2] = y + hw * s - hl * c;
    cx[3] = x + hw * c - hl * s;  cy[3] = y + hw * s + hl * c;
}

// One Sutherland-Hodgman clip pass. Polygon lives in a thread-private smem
// column (layout [slot][tid], stride TPB -> bank-conflict-free for any slot).
// Compaction "push" = predicated STS at computed address; no select chains.
// In-place safe: all INCAP slots are read into registers before any write.
// Reference semantics: keep = (val <= 0), crossing = strict sign change,
// frozen = empty result -> keep pre-clip polygon, stop clipping.
template <int INCAP>
__device__ __forceinline__ void clip_edge_smem(float a, float b, float c,
                                               float* __restrict__ sx,
                                               float* __restrict__ sy,
                                               int t, int& np, bool& frozen) {
    if (frozen || np <= 2) return;

    float rx[INCAP], ry[INCAP], v[INCAP];
#pragma unroll
    for (int j = 0; j < INCAP; j++) {
        rx[j] = sx[j * TPB + t];
        ry[j] = sy[j * TPB + t];
        v[j]  = a * rx[j] + b * ry[j] + c;
    }

    int nn = 0;
#pragma unroll
    for (int j = 0; j < INCAP; j++) {
        bool act  = (j < np);
        bool last = (j + 1 == np);
        const int j1 = (j + 1 < INCAP) ? (j + 1) : 0;
        float tv = last ? v[0]  : v[j1];
        float tx = last ? rx[0] : rx[j1];
        float ty = last ? ry[0] : ry[j1];

        bool keep = act && (v[j] <= 0.0f);
        bool crs  = act && (v[j] * tv < 0.0f);

        if (keep) {
            sx[nn * TPB + t] = rx[j];
            sy[nn * TPB + t] = ry[j];
            nn++;
        }
        if (crs) {
            float a2 = ty - ry[j];
            float b2 = rx[j] - tx;
            float c2 = tx * ry[j] - ty * rx[j];
            float wd = a * b2 - b * a2;
            float iw = __fdividef(1.0f, wd);
            sx[nn * TPB + t] = (b * c2 - c * b2) * iw;
            sy[nn * TPB + t] = (c * a2 - a * c2) * iw;
            nn++;
        }
    }

    if (nn > 0) np = nn;  // geometric bound: nn <= INCAP+1 <= 8
    else frozen = true;   // keep old polygon (reference semantics)
}

__global__ void __launch_bounds__(TPB, 7)
giou_kernel(const float* __restrict__ pred,
            const float* __restrict__ tgt,
            float* __restrict__ out, int n) {
    __shared__ float s_x[8 * TPB];
    __shared__ float s_y[8 * TPB];

    int t = threadIdx.x;
    int i = blockIdx.x * TPB + t;
    float giou = 0.0f;

    if (i < n) {
        const float2* pb = (const float2*)(pred + 6 * i);
        const float2* tb = (const float2*)(tgt + 6 * i);
        float2 p0 = __ldg(pb), p1 = __ldg(pb + 1), p2 = __ldg(pb + 2);
        float2 t0 = __ldg(tb), t1 = __ldg(tb + 1), t2 = __ldg(tb + 2);

        float pcx[4], pcy[4], tcx[4], tcy[4];
        box_corners(p0.x, p0.y, p1.x, p1.y, p2.x, p2.y, pcx, pcy);
        box_corners(t0.x, t0.y, t1.x, t1.y, t2.x, t2.y, tcx, tcy);

        // ---- init polygon (pred quad) in this thread's smem column ----
#pragma unroll
        for (int k = 0; k < 4; k++) {
            s_x[k * TPB + t] = pcx[k];
            s_y[k * TPB + t] = pcy[k];
        }
#pragma unroll
        for (int k = 4; k < 8; k++) {   // defined values in spare slots
            s_x[k * TPB + t] = pcx[0];
            s_y[k * TPB + t] = pcy[0];
        }
        int np = 4;
        bool frozen = false;

        // ---- clip by the 4 target half-planes ----
        {
            float a0 = tcy[1] - tcy[0], b0 = tcx[0] - tcx[1];
            float c0 = tcx[1] * tcy[0] - tcy[1] * tcx[0];
            clip_edge_smem<4>(a0, b0, c0, s_x, s_y, t, np, frozen);
            float a1 = tcy[2] - tcy[1], b1 = tcx[1] - tcx[2];
            float c1 = tcx[2] * tcy[1] - tcy[2] * tcx[1];
            clip_edge_smem<5>(a1, b1, c1, s_x, s_y, t, np, frozen);
            float a2 = tcy[3] - tcy[2], b2 = tcx[2] - tcx[3];
            float c2 = tcx[3] * tcy[2] - tcy[3] * tcx[2];
            clip_edge_smem<6>(a2, b2, c2, s_x, s_y, t, np, frozen);
            float a3 = tcy[0] - tcy[3], b3 = tcx[3] - tcx[0];
            float c3 = tcx[0] * tcy[3] - tcy[0] * tcx[3];
            clip_edge_smem<7>(a3, b3, c3, s_x, s_y, t, np, frozen);
        }

        // ---- shoelace over final polygon (read back once) ----
        float s2 = 0.0f;
        {
            float qx[8], qy[8];
#pragma unroll
            for (int k = 0; k < 8; k++) {
                qx[k] = s_x[k * TPB + t];
                qy[k] = s_y[k * TPB + t];
            }
#pragma unroll
            for (int j = 0; j < 8; j++) {
                bool act  = (j < np);
                bool last = (j + 1 == np);
                const int j1 = (j + 1) & 7;
                float nx = last ? qx[0] : qx[j1];
                float ny = last ? qy[0] : qy[j1];
                float tm = qx[j] * ny - qy[j] * nx;
                s2 += act ? tm : 0.0f;
            }
        }
        float inter = (np > 2) ? 0.5f * fabsf(s2) : 0.0f;

        float uni = p1.x * p1.y + t1.x * t1.y - inter;
        float iou = inter * __fdividef(1.0f, uni + 1e-16f);
        out[i] = iou;

        // ---- convex hull area (reference all-pairs form), antisymmetric:
        //      cross of edge (jj->ii) at k is -cross of (ii->jj) at k, and
        //      contrib(jj,ii) = -contrib(ii,jj): each unordered pair once.
        //      Hull points alias the corner arrays (no extra register image).
        float hs = 0.0f;
#pragma unroll
        for (int ii = 0; ii < 8; ii++) {
            float xi = (ii < 4) ? pcx[ii] : tcx[ii - 4];
            float yi = (ii < 4) ? pcy[ii] : tcy[ii - 4];
            float dx[8], dy[8];
#pragma unroll
            for (int k = 0; k < 8; k++) {
                float xk = (k < 4) ? pcx[k] : tcx[k - 4];
                float yk = (k < 4) ? pcy[k] : tcy[k - 4];
                dx[k] = xk - xi;
                dy[k] = yk - yi;
            }
#pragma unroll
            for (int jj = ii + 1; jj < 8; jj++) {
                float ex = dx[jj], ey = dy[jj];
                float len2 = ex * ex + ey * ey;
                bool okL = (len2 > 1e-12f);  // ii -> jj direction
                bool okR = okL;              // jj -> ii direction
#pragma unroll
                for (int k = 0; k < 8; k++) {
                    if (k == ii || k == jj) continue;  // cross == 0 there
                    float cr = ex * dy[k] - ey * dx[k];
                    okL = okL && (cr >= -1e-6f);
                    okR = okR && (cr <= 1e-6f);
                }
                float xj = (jj < 4) ? pcx[jj] : tcx[jj - 4];
                float yj = (jj < 4) ? pcy[jj] : tcy[jj - 4];
                float cij = xi * yj - yi * xj;
                hs += okL ? cij : 0.0f;
                hs += okR ? -cij : 0.0f;
            }
        }
        float hull = 0.5f * fabsf(hs);

        giou = 1.0f - (iou - (hull - uni) * __fdividef(1.0f, hull + 1e-16f));
    }

    // ---- deterministic in-kernel reduction ----
#pragma unroll
    for (int off = 16; off > 0; off >>= 1)
        giou += __shfl_down_sync(0xffffffffu, giou, off);

    __shared__ float wsum[TPB / 32];
    __shared__ bool isLast;
    if ((t & 31) == 0) wsum[t >> 5] = giou;
    __syncthreads();

    if (t == 0) {
        float bs = 0.0f;
#pragma unroll
        for (int w = 0; w < TPB / 32; w++) bs += wsum[w];
        g_partials[blockIdx.x] = bs;
        __threadfence();
        unsigned c = atomicAdd(&g_count, 1u);
        isLast = (c == gridDim.x - 1);
    }
    __syncthreads();

    if (isLast) {
        __threadfence();
        float v = 0.0f;
        for (int j = t; j < (int)gridDim.x; j += TPB)
            v += ((volatile float*)g_partials)[j];
#pragma unroll
        for (int off = 16; off > 0; off >>= 1)
            v += __shfl_down_sync(0xffffffffu, v, off);
        if ((t & 31) == 0) wsum[t >> 5] = v;
        __syncthreads();
        if (t == 0) {
            float tot = 0.0f;
#pragma unroll
            for (int w = 0; w < TPB / 32; w++) tot += wsum[w];
            out[n] = tot;
            g_count = 0;  // reset for next graph replay
        }
    }
}

extern "C" void kernel_launch(void* const* d_in, const int* in_sizes, int n_in,
                              void* d_out, int out_size) {
    const float* pred = (const float*)d_in[0];
    const float* tgt  = (const float*)d_in[1];
    float* out = (float*)d_out;
    int n = in_sizes[0] / 6;
    int nblocks = (n + TPB - 1) / TPB;
    giou_kernel<<<nblocks, TPB>>>(pred, tgt, out, n);
}

// round 6
// speedup vs baseline: 1.3930x; 1.0017x over previous
#include <cuda_runtime.h>
#include <math.h>

#define TPB 128
#define NPART 2048

__device__ float g_partials[NPART];
__device__ unsigned int g_count;

// One Sutherland-Hodgman clip pass. Polygon lives in a thread-private smem
// column (layout [slot][tid], stride TPB -> bank-conflict-free for any slot).
// Compaction "push" = predicated STS at computed address; no select chains.
// In-place safe: all INCAP slots are read into registers before any write.
// Reads of slots >= np are predicate-discarded, so garbage there is harmless.
// Reference semantics: keep = (val <= 0), crossing = strict sign change,
// frozen = empty result -> keep pre-clip polygon, stop clipping.
template <int INCAP>
__device__ __forceinline__ void clip_edge_smem(float a, float b, float c,
                                               float* __restrict__ sx,
                                               float* __restrict__ sy,
                                               int t, int& np, bool& frozen) {
    if (frozen || np <= 2) return;

    float rx[INCAP], ry[INCAP], v[INCAP];
#pragma unroll
    for (int j = 0; j < INCAP; j++) {
        rx[j] = sx[j * TPB + t];
        ry[j] = sy[j * TPB + t];
        v[j]  = a * rx[j] + b * ry[j] + c;
    }

    int nn = 0;
#pragma unroll
    for (int j = 0; j < INCAP; j++) {
        bool act  = (j < np);
        bool last = (j + 1 == np);
        const int j1 = (j + 1 < INCAP) ? (j + 1) : 0;
        float tv = last ? v[0]  : v[j1];
        float tx = last ? rx[0] : rx[j1];
        float ty = last ? ry[0] : ry[j1];

        bool keep = act && (v[j] <= 0.0f);
        bool crs  = act && (v[j] * tv < 0.0f);

        if (keep) {
            sx[nn * TPB + t] = rx[j];
            sy[nn * TPB + t] = ry[j];
            nn++;
        }
        if (crs) {
            float a2 = ty - ry[j];
            float b2 = rx[j] - tx;
            float c2 = tx * ry[j] - ty * rx[j];
            float wd = a * b2 - b * a2;
            float iw = __fdividef(1.0f, wd);
            sx[nn * TPB + t] = (b * c2 - c * b2) * iw;
            sy[nn * TPB + t] = (c * a2 - a * c2) * iw;
            nn++;
        }
    }

    if (nn > 0) np = nn;  // geometric bound: nn <= INCAP+1 <= 8
    else frozen = true;   // keep old polygon (reference semantics)
}

__global__ void __launch_bounds__(TPB, 8)
giou_kernel(const float* __restrict__ pred,
            const float* __restrict__ tgt,
            float* __restrict__ out, int n) {
    __shared__ float s_x[8 * TPB];   // clip polygon
    __shared__ float s_y[8 * TPB];
    __shared__ float c_x[8 * TPB];   // 8 original corners (0-3 pred, 4-7 tgt)
    __shared__ float c_y[8 * TPB];

    int t = threadIdx.x;
    int i = blockIdx.x * TPB + t;
    float giou = 0.0f;

    if (i < n) {
        const float2* pb = (const float2*)(pred + 6 * i);
        const float2* tb = (const float2*)(tgt + 6 * i);
        float2 p0 = __ldg(pb), p1 = __ldg(pb + 1), p2 = __ldg(pb + 2);
        float2 t0 = __ldg(tb), t1 = __ldg(tb + 1), t2 = __ldg(tb + 2);
        float area_sum = p1.x * p1.y + t1.x * t1.y;  // pa + ta

        // ---- corners straight into smem (no persistent register image) ----
        {
            // pred box: also initializes the clip polygon (slots 0-3)
            float rinv = rsqrtf(fmaf(p2.x, p2.x, p2.y * p2.y));
            float cth = p2.y * rinv, sth = p2.x * rinv;
            float hw = 0.5f * p1.x, hl = 0.5f * p1.y;
            float cx0 = p0.x - hw * cth - hl * sth, cy0 = p0.y - hw * sth + hl * cth;
            float cx1 = p0.x - hw * cth + hl * sth, cy1 = p0.y - hw * sth - hl * cth;
            float cx2 = p0.x + hw * cth + hl * sth, cy2 = p0.y + hw * sth - hl * cth;
            float cx3 = p0.x + hw * cth - hl * sth, cy3 = p0.y + hw * sth + hl * cth;
            c_x[0 * TPB + t] = cx0;  c_y[0 * TPB + t] = cy0;
            c_x[1 * TPB + t] = cx1;  c_y[1 * TPB + t] = cy1;
            c_x[2 * TPB + t] = cx2;  c_y[2 * TPB + t] = cy2;
            c_x[3 * TPB + t] = cx3;  c_y[3 * TPB + t] = cy3;
            s_x[0 * TPB + t] = cx0;  s_y[0 * TPB + t] = cy0;
            s_x[1 * TPB + t] = cx1;  s_y[1 * TPB + t] = cy1;
            s_x[2 * TPB + t] = cx2;  s_y[2 * TPB + t] = cy2;
            s_x[3 * TPB + t] = cx3;  s_y[3 * TPB + t] = cy3;
        }
        {
            // target box
            float rinv = rsqrtf(fmaf(t2.x, t2.x, t2.y * t2.y));
            float cth = t2.y * rinv, sth = t2.x * rinv;
            float hw = 0.5f * t1.x, hl = 0.5f * t1.y;
            c_x[4 * TPB + t] = t0.x - hw * cth - hl * sth;
            c_y[4 * TPB + t] = t0.y - hw * sth + hl * cth;
            c_x[5 * TPB + t] = t0.x - hw * cth + hl * sth;
            c_y[5 * TPB + t] = t0.y - hw * sth - hl * cth;
            c_x[6 * TPB + t] = t0.x + hw * cth + hl * sth;
            c_y[6 * TPB + t] = t0.y + hw * sth - hl * cth;
            c_x[7 * TPB + t] = t0.x + hw * cth - hl * sth;
            c_y[7 * TPB + t] = t0.y + hw * sth + hl * cth;
        }

        // ---- clip by the 4 target half-planes (planes built JIT from smem) ----
        int np = 4;
        bool frozen = false;
#pragma unroll
        for (int e = 0; e < 4; e++) {
            const int e1 = (e + 1) & 3;
            float Px = c_x[(4 + e) * TPB + t],  Py = c_y[(4 + e) * TPB + t];
            float Qx = c_x[(4 + e1) * TPB + t], Qy = c_y[(4 + e1) * TPB + t];
            float a = Qy - Py;
            float b = Px - Qx;
            float c = Qx * Py - Qy * Px;
            if (e == 0)      clip_edge_smem<4>(a, b, c, s_x, s_y, t, np, frozen);
            else if (e == 1) clip_edge_smem<5>(a, b, c, s_x, s_y, t, np, frozen);
            else if (e == 2) clip_edge_smem<6>(a, b, c, s_x, s_y, t, np, frozen);
            else             clip_edge_smem<7>(a, b, c, s_x, s_y, t, np, frozen);
        }

        // ---- shoelace over final polygon ----
        float s2 = 0.0f;
        {
            float qx[8], qy[8];
#pragma unroll
            for (int k = 0; k < 8; k++) {
                qx[k] = s_x[k * TPB + t];
                qy[k] = s_y[k * TPB + t];
            }
#pragma unroll
            for (int j = 0; j < 8; j++) {
                bool act  = (j < np);
                bool last = (j + 1 == np);
                const int j1 = (j + 1) & 7;
                float nx = last ? qx[0] : qx[j1];
                float ny = last ? qy[0] : qy[j1];
                float tm = qx[j] * ny - qy[j] * nx;
                s2 += act ? tm : 0.0f;
            }
        }
        float inter = (np > 2) ? 0.5f * fabsf(s2) : 0.0f;

        float uni = area_sum - inter;
        float iou = inter * __fdividef(1.0f, uni + 1e-16f);
        out[i] = iou;

        // ---- convex hull area (reference all-pairs form), antisymmetric:
        //      each unordered pair once; contribution via the diff identity
        //      x_i*y_j - y_i*x_j == x_i*dy[j] - y_i*dx[j]  (exact algebra).
        float hs = 0.0f;
#pragma unroll
        for (int ii = 0; ii < 8; ii++) {
            float xi = c_x[ii * TPB + t];
            float yi = c_y[ii * TPB + t];
            float dx[8], dy[8];
#pragma unroll
            for (int k = 0; k < 8; k++) {
                dx[k] = c_x[k * TPB + t] - xi;
                dy[k] = c_y[k * TPB + t] - yi;
            }
#pragma unroll
            for (int jj = ii + 1; jj < 8; jj++) {
                float ex = dx[jj], ey = dy[jj];
                float len2 = ex * ex + ey * ey;
                bool okL = (len2 > 1e-12f);  // ii -> jj direction
                bool okR = okL;              // jj -> ii direction
#pragma unroll
                for (int k = 0; k < 8; k++) {
                    if (k == ii || k == jj) continue;  // cross == 0 there
                    float cr = ex * dy[k] - ey * dx[k];
                    okL = okL && (cr >= -1e-6f);
                    okR = okR && (cr <= 1e-6f);
                }
                float cij = xi * ey - yi * ex;  // == xi*yj - yi*xj
                hs += okL ? cij : 0.0f;
                hs += okR ? -cij : 0.0f;
            }
        }
        float hull = 0.5f * fabsf(hs);

        giou = 1.0f - (iou - (hull - uni) * __fdividef(1.0f, hull + 1e-16f));
    }

    // ---- deterministic in-kernel reduction ----
#pragma unroll
    for (int off = 16; off > 0; off >>= 1)
        giou += __shfl_down_sync(0xffffffffu, giou, off);

    __shared__ float wsum[TPB / 32];
    __shared__ bool isLast;
    if ((t & 31) == 0) wsum[t >> 5] = giou;
    __syncthreads();

    if (t == 0) {
        float bs = 0.0f;
#pragma unroll
        for (int w = 0; w < TPB / 32; w++) bs += wsum[w];
        g_partials[blockIdx.x] = bs;
        __threadfence();
        unsigned c = atomicAdd(&g_count, 1u);
        isLast = (c == gridDim.x - 1);
    }
    __syncthreads();

    if (isLast) {
        __threadfence();
        float v = 0.0f;
        for (int j = t; j < (int)gridDim.x; j += TPB)
            v += ((volatile float*)g_partials)[j];
#pragma unroll
        for (int off = 16; off > 0; off >>= 1)
            v += __shfl_down_sync(0xffffffffu, v, off);
        if ((t & 31) == 0) wsum[t >> 5] = v;
        __syncthreads();
        if (t == 0) {
            float tot = 0.0f;
#pragma unroll
            for (int w = 0; w < TPB / 32; w++) tot += wsum[w];
            out[n] = tot;
            g_count = 0;  // reset for next graph replay
        }
    }
}

extern "C" void kernel_launch(void* const* d_in, const int* in_sizes, int n_in,
                              void* d_out, int out_size) {
    const float* pred = (const float*)d_in[0];
    const float* tgt  = (const float*)d_in[1];
    float* out = (float*)d_out;
    int n = in_sizes[0] / 6;
    int nblocks = (n + TPB - 1) / TPB;
    giou_kernel<<<nblocks, TPB>>>(pred, tgt, out, n);
}

// round 7
// speedup vs baseline: 1.5570x; 1.1178x over previous
#include <cuda_runtime.h>
#include <math.h>

#define TPB 128
#define NPART 2048

__device__ float g_partials[NPART];
__device__ unsigned int g_count;

// One Sutherland-Hodgman clip pass. Polygon lives in a thread-private smem
// column of float2 (layout [slot][tid], stride TPB -> conflict-free 64-bit
// accesses). Compaction "push" = predicated STS.64 + pointer bump.
// In-place safe: all INCAP slots are read into registers before any write.
// Reads of slots >= np are predicate-discarded, so garbage there is harmless.
// Reference semantics: keep = (val <= 0), crossing = strict sign change,
// frozen = empty result -> keep pre-clip polygon, stop clipping.
template <int INCAP>
__device__ __forceinline__ void clip_edge_smem(float a, float b, float c,
                                               float2* __restrict__ sp,
                                               int t, int& np, bool& frozen) {
    if (frozen || np <= 2) return;

    float2 r[INCAP];
    float v[INCAP];
#pragma unroll
    for (int j = 0; j < INCAP; j++) {
        r[j] = sp[j * TPB + t];
        v[j] = a * r[j].x + b * r[j].y + c;
    }

    float2* wp = sp + t;
    int nn = 0;
#pragma unroll
    for (int j = 0; j < INCAP; j++) {
        bool act  = (j < np);
        bool last = (j + 1 == np);
        const int j1 = (j + 1 < INCAP) ? (j + 1) : 0;
        float tv = last ? v[0]   : v[j1];
        float tx = last ? r[0].x : r[j1].x;
        float ty = last ? r[0].y : r[j1].y;

        bool keep = act && (v[j] <= 0.0f);
        bool crs  = act && (v[j] * tv < 0.0f);

        if (keep) {
            *wp = r[j];
            wp += TPB;
            nn++;
        }
        if (crs) {
            float a2 = ty - r[j].y;
            float b2 = r[j].x - tx;
            float c2 = tx * r[j].y - ty * r[j].x;
            float wd = a * b2 - b * a2;
            float iw = __fdividef(1.0f, wd);
            float2 ip;
            ip.x = (b * c2 - c * b2) * iw;
            ip.y = (c * a2 - a * c2) * iw;
            *wp = ip;
            wp += TPB;
            nn++;
        }
    }

    if (nn > 0) np = nn;  // geometric bound: nn <= INCAP+1 <= 8
    else frozen = true;   // keep old polygon (reference semantics)
}

__global__ void __launch_bounds__(TPB, 8)
giou_kernel(const float* __restrict__ pred,
            const float* __restrict__ tgt,
            float* __restrict__ out, int n) {
    __shared__ float2 s_xy[8 * TPB];   // clip polygon
    __shared__ float2 c_xy[8 * TPB];   // 8 corners (0-3 pred, 4-7 tgt)

    int t = threadIdx.x;
    int i = blockIdx.x * TPB + t;
    float giou = 0.0f;

    if (i < n) {
        const float2* pb = (const float2*)(pred + 6 * i);
        const float2* tb = (const float2*)(tgt + 6 * i);
        float2 p0 = __ldg(pb), p1 = __ldg(pb + 1), p2 = __ldg(pb + 2);
        float2 t0 = __ldg(tb), t1 = __ldg(tb + 1), t2 = __ldg(tb + 2);
        float area_sum = p1.x * p1.y + t1.x * t1.y;  // pa + ta

        // ---- corners into smem (float2); pred corners also seed polygon ----
        {
            float rinv = rsqrtf(fmaf(p2.x, p2.x, p2.y * p2.y));
            float cth = p2.y * rinv, sth = p2.x * rinv;
            float hw = 0.5f * p1.x, hl = 0.5f * p1.y;
            float2 c0 = make_float2(p0.x - hw * cth - hl * sth, p0.y - hw * sth + hl * cth);
            float2 c1 = make_float2(p0.x - hw * cth + hl * sth, p0.y - hw * sth - hl * cth);
            float2 c2 = make_float2(p0.x + hw * cth + hl * sth, p0.y + hw * sth - hl * cth);
            float2 c3 = make_float2(p0.x + hw * cth - hl * sth, p0.y + hw * sth + hl * cth);
            c_xy[0 * TPB + t] = c0;  s_xy[0 * TPB + t] = c0;
            c_xy[1 * TPB + t] = c1;  s_xy[1 * TPB + t] = c1;
            c_xy[2 * TPB + t] = c2;  s_xy[2 * TPB + t] = c2;
            c_xy[3 * TPB + t] = c3;  s_xy[3 * TPB + t] = c3;
        }
        {
            float rinv = rsqrtf(fmaf(t2.x, t2.x, t2.y * t2.y));
            float cth = t2.y * rinv, sth = t2.x * rinv;
            float hw = 0.5f * t1.x, hl = 0.5f * t1.y;
            c_xy[4 * TPB + t] = make_float2(t0.x - hw * cth - hl * sth, t0.y - hw * sth + hl * cth);
            c_xy[5 * TPB + t] = make_float2(t0.x - hw * cth + hl * sth, t0.y - hw * sth - hl * cth);
            c_xy[6 * TPB + t] = make_float2(t0.x + hw * cth + hl * sth, t0.y + hw * sth - hl * cth);
            c_xy[7 * TPB + t] = make_float2(t0.x + hw * cth - hl * sth, t0.y + hw * sth + hl * cth);
        }

        // ---- clip by the 4 target half-planes (planes built JIT from smem) ----
        int np = 4;
        bool frozen = false;
#pragma unroll
        for (int e = 0; e < 4; e++) {
            const int e1 = (e + 1) & 3;
            float2 P = c_xy[(4 + e) * TPB + t];
            float2 Q = c_xy[(4 + e1) * TPB + t];
            float a = Q.y - P.y;
            float b = P.x - Q.x;
            float c = Q.x * P.y - Q.y * P.x;
            if (e == 0)      clip_edge_smem<4>(a, b, c, s_xy, t, np, frozen);
            else if (e == 1) clip_edge_smem<5>(a, b, c, s_xy, t, np, frozen);
            else if (e == 2) clip_edge_smem<6>(a, b, c, s_xy, t, np, frozen);
            else             clip_edge_smem<7>(a, b, c, s_xy, t, np, frozen);
        }

        // ---- shoelace over final polygon ----
        float s2 = 0.0f;
        {
            float2 q[8];
#pragma unroll
            for (int k = 0; k < 8; k++) q[k] = s_xy[k * TPB + t];
#pragma unroll
            for (int j = 0; j < 8; j++) {
                bool act  = (j < np);
                bool last = (j + 1 == np);
                const int j1 = (j + 1) & 7;
                float nx = last ? q[0].x : q[j1].x;
                float ny = last ? q[0].y : q[j1].y;
                float tm = q[j].x * ny - q[j].y * nx;
                s2 += act ? tm : 0.0f;
            }
        }
        float inter = (np > 2) ? 0.5f * fabsf(s2) : 0.0f;

        float uni = area_sum - inter;
        float iou = inter * __fdividef(1.0f, uni + 1e-16f);
        out[i] = iou;

        // ---- convex hull area (reference all-pairs form) ----
        // Corners now live in registers (clip pressure is over).
        // Antisymmetry: each unordered pair once, both directed validities
        // via min/max trees (depth 3) instead of deep predicate chains.
        float2 P[8];
#pragma unroll
        for (int k = 0; k < 8; k++) P[k] = c_xy[k * TPB + t];

        float hs = 0.0f;
#pragma unroll
        for (int ii = 0; ii < 8; ii++) {
            float dx[8], dy[8];
#pragma unroll
            for (int k = 0; k < 8; k++) {
                dx[k] = P[k].x - P[ii].x;
                dy[k] = P[k].y - P[ii].y;
            }
#pragma unroll
            for (int jj = ii + 1; jj < 8; jj++) {
                float ex = dx[jj], ey = dy[jj];
                float cr[6];
                int c6 = 0;
#pragma unroll
                for (int k = 0; k < 8; k++) {
                    if (k == ii || k == jj) continue;  // cross == 0 there
                    cr[c6++] = ex * dy[k] - ey * dx[k];
                }
                float mn = fminf(fminf(fminf(cr[0], cr[1]), fminf(cr[2], cr[3])),
                                 fminf(cr[4], cr[5]));
                float mx = fmaxf(fmaxf(fmaxf(cr[0], cr[1]), fmaxf(cr[2], cr[3])),
                                 fmaxf(cr[4], cr[5]));
                float len2 = ex * ex + ey * ey;
                bool okL = (len2 > 1e-12f) && (mn >= -1e-6f);  // ii -> jj
                bool okR = (len2 > 1e-12f) && (mx <= 1e-6f);   // jj -> ii
                float cij = P[ii].x * ey - P[ii].y * ex;  // == xi*yj - yi*xj
                hs += okL ? cij : 0.0f;
                hs += okR ? -cij : 0.0f;
            }
        }
        float hull = 0.5f * fabsf(hs);

        giou = 1.0f - (iou - (hull - uni) * __fdividef(1.0f, hull + 1e-16f));
    }

    // ---- deterministic in-kernel reduction ----
#pragma unroll
    for (int off = 16; off > 0; off >>= 1)
        giou += __shfl_down_sync(0xffffffffu, giou, off);

    __shared__ float wsum[TPB / 32];
    __shared__ bool isLast;
    if ((t & 31) == 0) wsum[t >> 5] = giou;
    __syncthreads();

    if (t == 0) {
        float bs = 0.0f;
#pragma unroll
        for (int w = 0; w < TPB / 32; w++) bs += wsum[w];
        g_partials[blockIdx.x] = bs;
        __threadfence();
        unsigned c = atomicAdd(&g_count, 1u);
        isLast = (c == gridDim.x - 1);
    }
    __syncthreads();

    if (isLast) {
        __threadfence();
        float v = 0.0f;
        for (int j = t; j < (int)gridDim.x; j += TPB)
            v += ((volatile float*)g_partials)[j];
#pragma unroll
        for (int off = 16; off > 0; off >>= 1)
            v += __shfl_down_sync(0xffffffffu, v, off);
        if ((t & 31) == 0) wsum[t >> 5] = v;
        __syncthreads();
        if (t == 0) {
            float tot = 0.0f;
#pragma unroll
            for (int w = 0; w < TPB / 32; w++) tot += wsum[w];
            out[n] = tot;
            g_count = 0;  // reset for next graph replay
        }
    }
}

extern "C" void kernel_launch(void* const* d_in, const int* in_sizes, int n_in,
                              void* d_out, int out_size) {
    const float* pred = (const float*)d_in[0];
    const float* tgt  = (const float*)d_in[1];
    float* out = (float*)d_out;
    int n = in_sizes[0] / 6;
    int nblocks = (n + TPB - 1) / TPB;
    giou_kernel<<<nblocks, TPB>>>(pred, tgt, out, n);
}